// round 14
// baseline (speedup 1.0000x reference)
#include <cuda_runtime.h>
#include <math.h>

#define NN 100000
#define NE 1600000
#define F3 32
#define PSTRIDE 96          // padded CSR stride; Poisson(16) degrees
#define NB 148              // co-resident blocks (1/SM x 148 min-SM-count)
#define TPB 1024
#define NTH (NB * TPB)
#define NTILE128 782        // ceil(NN/128)

// ---------------- scratch ----------------
__device__ float g_h0[NN * 64];
__device__ float g_h1[NN * 64];
__device__ int   g_cursor[NN];
__device__ int   g_colp[NN * PSTRIDE];
__device__ float g_meansum[F3];
__device__ float g_ctx[F3];
__device__ float g_pooled[F3];
__device__ unsigned g_cnt[16];
__device__ unsigned g_gen[16];

// ---------------- f32x2 helpers ----------------
__device__ __forceinline__ unsigned long long pk2(float lo, float hi) {
    unsigned long long r;
    asm("mov.b64 %0, {%1, %2};" : "=l"(r) : "f"(lo), "f"(hi));
    return r;
}
__device__ __forceinline__ float2 up2(unsigned long long v) {
    float2 r;
    asm("mov.b64 {%0, %1}, %2;" : "=f"(r.x), "=f"(r.y) : "l"(v));
    return r;
}
__device__ __forceinline__ void fma2(unsigned long long& acc,
                                     unsigned long long a, unsigned long long b) {
    asm("fma.rn.f32x2 %0, %1, %2, %0;" : "+l"(acc) : "l"(a), "l"(b));
}

// ---------------- grid barrier (all NB blocks co-resident) ----------------
__device__ __forceinline__ void gridbar(int b) {
    __syncthreads();
    if (threadIdx.x == 0) {
        volatile unsigned* vg = (volatile unsigned*)&g_gen[b];
        unsigned snap = *vg;
        __threadfence();
        unsigned old = atomicAdd(&g_cnt[b], 1u);
        if (old == NB - 1) {
            g_cnt[b] = 0;
            __threadfence();
            atomicAdd(&g_gen[b], 1u);
        } else {
            while (*vg == snap) {}
        }
        __threadfence();
    }
    __syncthreads();
}

// ---------------- producer: gather + x-load one 128-node tile ----------------
// 16 producer warps (pwid 0..15), each owns 8 nodes.
__device__ __forceinline__ void gather_tile(
    int tile, const float* __restrict__ x,
    float (*sA)[64], float (*sX)[64], int pwid, int lane)
{
    const int tile0 = tile * 128;
    const int nval = (NN - tile0 < 128) ? (NN - tile0) : 128;
    const int half = lane >> 4;
    const int lcol = lane & 15;
    const float4* __restrict__ x4 = (const float4*)x;
    const float2* __restrict__ x2 = (const float2*)x;

#pragma unroll
    for (int j = 0; j < 8; j++) {
        int nl = pwid * 8 + j;
        if (nl >= nval) break;
        int n = tile0 + nl;
        // x row (float2 by full warp = 256B coalesced)
        ((float2*)&sX[nl][0])[lane] = __ldg(&x2[n * 32 + lane]);
        // gather: half-warp split edges, full-row float4 loads
        int d = g_cursor[n];
        int dc = d < PSTRIDE ? d : PSTRIDE;
        const int* __restrict__ cb = &g_colp[n * PSTRIDE];
        float4 a4 = make_float4(0.f, 0.f, 0.f, 0.f);
        int c = 0;
        for (; c + 8 <= dc; c += 8) {
            int4 s4 = __ldg((const int4*)&cb[c + half * 4]);
            float4 v0 = __ldg(&x4[s4.x * 16 + lcol]);
            float4 v1 = __ldg(&x4[s4.y * 16 + lcol]);
            float4 v2 = __ldg(&x4[s4.z * 16 + lcol]);
            float4 v3 = __ldg(&x4[s4.w * 16 + lcol]);
            a4.x += v0.x + v1.x + v2.x + v3.x;
            a4.y += v0.y + v1.y + v2.y + v3.y;
            a4.z += v0.z + v1.z + v2.z + v3.z;
            a4.w += v0.w + v1.w + v2.w + v3.w;
        }
        for (int e = c + half; e < dc; e += 2) {
            int s = __ldg(&cb[e]);
            float4 v = __ldg(&x4[s * 16 + lcol]);
            a4.x += v.x; a4.y += v.y; a4.z += v.z; a4.w += v.w;
        }
        a4.x += __shfl_xor_sync(0xffffffffu, a4.x, 16);
        a4.y += __shfl_xor_sync(0xffffffffu, a4.y, 16);
        a4.z += __shfl_xor_sync(0xffffffffu, a4.z, 16);
        a4.w += __shfl_xor_sync(0xffffffffu, a4.w, 16);
        float inv = 1.0f / fmaxf((float)d, 1.0f);
        if (half == 0) {
            a4.x *= inv; a4.y *= inv; a4.z *= inv; a4.w *= inv;
            ((float4*)&sA[nl][0])[lcol] = a4;
        }
    }
}

// ---------------- consumer: FFMA2 dual GEMM + norm + store ----------------
// 16 consumer warps = 512 threads (ctid 0..511).
template <int FOUT, bool RELU>
__device__ __forceinline__ void gemm_tile(
    int tile, const float* __restrict__ bias_p, float* __restrict__ out,
    const float* sWl, const float* sWr,
    const float (*sA)[64], const float (*sX)[64], int ctid)
{
    const int tile0 = tile * 128;
    const int nval = (NN - tile0 < 128) ? (NN - tile0) : 128;
    const int CG = FOUT / 4;        // threads per node (16 or 8)
    const int NT = 512 / CG;        // node groups (32 or 64)
    const int TM = 128 / NT;        // nodes per thread (4 or 2)
    const int colg = ctid % CG;
    const int nodeb = (ctid / CG) * TM;

    unsigned long long acc01[TM], acc23[TM];
    {
        float4 bv = __ldg((const float4*)&bias_p[colg * 4]);
        unsigned long long b01 = pk2(bv.x, bv.y);
        unsigned long long b23 = pk2(bv.z, bv.w);
#pragma unroll
        for (int m = 0; m < TM; m++) { acc01[m] = b01; acc23[m] = b23; }
    }
#pragma unroll
    for (int k4 = 0; k4 < 16; k4++) {
        float4 av[TM], xv[TM];
#pragma unroll
        for (int m = 0; m < TM; m++) {
            av[m] = *(const float4*)&sA[nodeb + m][k4 * 4];
            xv[m] = *(const float4*)&sX[nodeb + m][k4 * 4];
        }
#pragma unroll
        for (int kk = 0; kk < 4; kk++) {
            ulonglong2 wl2 = *(const ulonglong2*)&sWl[(k4 * 4 + kk) * FOUT + colg * 4];
            ulonglong2 wr2 = *(const ulonglong2*)&sWr[(k4 * 4 + kk) * FOUT + colg * 4];
#pragma unroll
            for (int m = 0; m < TM; m++) {
                float a = (kk == 0) ? av[m].x : (kk == 1) ? av[m].y : (kk == 2) ? av[m].z : av[m].w;
                float xx = (kk == 0) ? xv[m].x : (kk == 1) ? xv[m].y : (kk == 2) ? xv[m].z : xv[m].w;
                unsigned long long aa = pk2(a, a);
                unsigned long long xp = pk2(xx, xx);
                fma2(acc01[m], aa, wl2.x);
                fma2(acc23[m], aa, wl2.y);
                fma2(acc01[m], xp, wr2.x);
                fma2(acc23[m], xp, wr2.y);
            }
        }
    }
#pragma unroll
    for (int m = 0; m < TM; m++) {
        float2 v01 = up2(acc01[m]);
        float2 v23 = up2(acc23[m]);
        float ss = v01.x * v01.x + v01.y * v01.y + v23.x * v23.x + v23.y * v23.y;
#pragma unroll
        for (int o = CG >> 1; o > 0; o >>= 1)
            ss += __shfl_xor_sync(0xffffffffu, ss, o);
        float inv = 1.0f / fmaxf(sqrtf(ss), 1e-12f);
        float4 v;
        v.x = v01.x * inv; v.y = v01.y * inv;
        v.z = v23.x * inv; v.w = v23.y * inv;
        if (RELU) {
            v.x = fmaxf(v.x, 0.f); v.y = fmaxf(v.y, 0.f);
            v.z = fmaxf(v.z, 0.f); v.w = fmaxf(v.w, 0.f);
        }
        int nl = nodeb + m;
        if (nl < nval)
            *(float4*)&out[(tile0 + nl) * FOUT + colg * 4] = v;
    }
}

// ---------------- pipelined layer phase ----------------
template <int FOUT, bool RELU>
__device__ void layer_phase(
    const float* __restrict__ x,
    const float* __restrict__ Wl, const float* __restrict__ bias_p,
    const float* __restrict__ Wr, float* __restrict__ out,
    float* sWl, float* sWr, float (*sA2)[128][64], float (*sX2)[128][64])
{
    const int tid = threadIdx.x;
    const int lane = tid & 31;
    const int wid = tid >> 5;      // 0..31
    const int bid = blockIdx.x;

    // stage weights once per phase (all 1024 threads)
    {
        const float4* Wl4 = (const float4*)Wl;
        const float4* Wr4 = (const float4*)Wr;
        for (int i = tid; i < 64 * FOUT / 4; i += TPB) {
            ((float4*)sWl)[i] = Wl4[i];
            ((float4*)sWr)[i] = Wr4[i];
        }
    }

    const bool producer = (wid >= 16);
    const int pwid = wid - 16;
    const int ctid = tid;          // consumer tid 0..511 when wid<16
    const int K = (NTILE128 - bid + NB - 1) / NB;   // tiles for this block (5 or 6)

    __syncthreads();               // weights + buffers ready

    // prologue: producers fill buffer 0 with tile k=0
    if (producer) gather_tile(bid, x, sA2[0], sX2[0], pwid, lane);
    __syncthreads();

    for (int k = 0; k < K; k++) {
        if (!producer) {
            gemm_tile<FOUT, RELU>(bid + k * NB, bias_p, out, sWl, sWr,
                                  sA2[k & 1], sX2[k & 1], ctid);
        } else if (k + 1 < K) {
            gather_tile(bid + (k + 1) * NB, x, sA2[(k + 1) & 1], sX2[(k + 1) & 1],
                        pwid, lane);
        }
        __syncthreads();
    }
}

// ---------------- the single persistent kernel ----------------
__global__ void __launch_bounds__(TPB, 1) k_all(
    const float* __restrict__ feats, const void* __restrict__ edges,
    const float* __restrict__ W1l, const float* __restrict__ b1, const float* __restrict__ W1r,
    const float* __restrict__ W2l, const float* __restrict__ b2, const float* __restrict__ W2r,
    const float* __restrict__ W3l, const float* __restrict__ b3, const float* __restrict__ W3r,
    const float* __restrict__ Watt,
    const float* __restrict__ Wfc, const float* __restrict__ bfc,
    const float* __restrict__ Ws,  const float* __restrict__ bs,
    float* __restrict__ out)
{
    __shared__ float sWl[64 * 64];
    __shared__ float sWr[64 * 64];
    __shared__ float sA2[2][128][64];
    __shared__ float sX2[2][128][64];
    __shared__ float sPart[F3];
    __shared__ int s_any;

    const int tid = threadIdx.x;
    const int bid = blockIdx.x;
    const int gtid = bid * TPB + tid;
    const int lane = tid & 31;
    const int wid = tid >> 5;

    // ---- phase A: zero scratch ----
    for (int i = gtid; i < NN; i += NTH) g_cursor[i] = 0;
    if (gtid < F3) { g_meansum[gtid] = 0.f; g_pooled[gtid] = 0.f; }
    gridbar(0);

    // ---- phase B: CSR build ----
    {
        if (tid == 0) s_any = 0;
        __syncthreads();
        const unsigned* w = (const unsigned*)edges;
        if (tid < 256 && w[2 * tid + 1] != 0u) atomicOr(&s_any, 1);
        __syncthreads();
        const bool is64 = (s_any == 0);
        for (int i = gtid; i < NE; i += NTH) {
            int s, t;
            if (is64) {
                s = (int)((const long long*)edges)[i];
                t = (int)((const long long*)edges)[NE + i];
            } else {
                s = ((const int*)edges)[i];
                t = ((const int*)edges)[NE + i];
            }
            int pos = atomicAdd(&g_cursor[t], 1);
            if (pos < PSTRIDE) g_colp[t * PSTRIDE + pos] = s;
        }
    }
    gridbar(1);

    // ---- phases C/D/E: three pipelined layers ----
    layer_phase<64, true >(feats, W1l, b1, W1r, g_h0, sWl, sWr, sA2, sX2);
    gridbar(2);
    layer_phase<64, true >(g_h0,  W2l, b2, W2r, g_h1, sWl, sWr, sA2, sX2);
    gridbar(3);
    layer_phase<32, false>(g_h1,  W3l, b3, W3r, g_h0, sWl, sWr, sA2, sX2);
    gridbar(4);

    const float* __restrict__ h3 = g_h0;   // [NN, 32]

    // ---- phase F: mean over nodes ----
    {
        if (tid < F3) sPart[tid] = 0.f;
        __syncthreads();
        float acc = 0.f;
        int gw = bid * 32 + wid;
        for (int n = gw; n < NN; n += NB * 32) acc += h3[n * F3 + lane];
        atomicAdd(&sPart[lane], acc);
        __syncthreads();
        if (tid < F3) atomicAdd(&g_meansum[tid], sPart[tid]);
    }
    gridbar(5);

    // ---- phase G: context ----
    if (bid == 0 && wid == 0) {
        float s = 0.f;
        const float invN = 1.0f / (float)NN;
        for (int k = 0; k < F3; k++)
            s += (g_meansum[k] * invN) * __ldg(&Watt[k * F3 + lane]);
        g_ctx[lane] = tanhf(s);
    }
    gridbar(6);

    // ---- phase H: attention pooling ----
    {
        if (tid < F3) sPart[tid] = 0.f;
        __syncthreads();
        float ctx = g_ctx[lane];
        float acc = 0.f;
        int gw = bid * 32 + wid;
        for (int n = gw; n < NN; n += NB * 32) {
            float v = h3[n * F3 + lane];
            float d = v * ctx;
#pragma unroll
            for (int o = 16; o > 0; o >>= 1) d += __shfl_xor_sync(0xffffffffu, d, o);
            float att = 1.0f / (1.0f + expf(-d));
            acc += att * v;
        }
        atomicAdd(&sPart[lane], acc);
        __syncthreads();
        if (tid < F3) atomicAdd(&g_pooled[tid], sPart[tid]);
    }
    gridbar(7);

    // ---- phase I: final MLP ----
    if (bid == 0 && wid == 0) {
        float hid = 0.f;
        if (lane < 16) {
            float s = __ldg(&bfc[lane]);
            for (int j = 0; j < F3; j++) s += g_pooled[j] * __ldg(&Wfc[j * 16 + lane]);
            hid = fmaxf(s, 0.f);
        }
        float term = (lane < 16) ? hid * __ldg(&Ws[lane]) : 0.f;
#pragma unroll
        for (int o = 16; o > 0; o >>= 1) term += __shfl_xor_sync(0xffffffffu, term, o);
        if (lane == 0) out[0] = 1.0f / (1.0f + expf(-(term + __ldg(&bs[0]))));
    }
}

// ---------------- launch ----------------
extern "C" void kernel_launch(void* const* d_in, const int* in_sizes, int n_in,
                              void* d_out, int out_size) {
    const float* feats = (const float*)d_in[0];
    const void*  edges = d_in[1];
    const float* W1l = (const float*)d_in[2];
    const float* b1  = (const float*)d_in[3];
    const float* W1r = (const float*)d_in[4];
    const float* W2l = (const float*)d_in[5];
    const float* b2  = (const float*)d_in[6];
    const float* W2r = (const float*)d_in[7];
    const float* W3l = (const float*)d_in[8];
    const float* b3  = (const float*)d_in[9];
    const float* W3r = (const float*)d_in[10];
    const float* Watt= (const float*)d_in[11];
    const float* Wfc = (const float*)d_in[12];
    const float* bfc = (const float*)d_in[13];
    const float* Ws  = (const float*)d_in[14];
    const float* bs  = (const float*)d_in[15];
    float* out = (float*)d_out;

    k_all<<<NB, TPB>>>(feats, edges,
                       W1l, b1, W1r, W2l, b2, W2r, W3l, b3, W3r,
                       Watt, Wfc, bfc, Ws, bs, out);
}

// round 15
// speedup vs baseline: 1.2217x; 1.2217x over previous
#include <cuda_runtime.h>
#include <math.h>

#define NN 100000
#define NE 1600000
#define F3 32
#define PSTRIDE 96          // padded CSR stride; Poisson(16) degrees
#define NB 296              // co-resident blocks (2/SM x 148 min-SM-count)
#define TPB 512
#define NTH (NB * TPB)
#define TILEN 113           // nodes per tile: 296 blocks x 3 tiles x 113 = 100344 >= NN
#define TPB3 3              // tiles per block (exact)

// ---------------- scratch ----------------
__device__ float g_h0[NN * 64];
__device__ float g_h1[NN * 64];
__device__ int   g_cursor[NN];
__device__ int   g_colp[NN * PSTRIDE];
__device__ float g_meansum[F3];
__device__ float g_ctx[F3];
__device__ float g_pooled[F3];
__device__ unsigned g_cnt[16];
__device__ unsigned g_gen[16];

// ---------------- f32x2 helpers ----------------
__device__ __forceinline__ unsigned long long pk2(float lo, float hi) {
    unsigned long long r;
    asm("mov.b64 %0, {%1, %2};" : "=l"(r) : "f"(lo), "f"(hi));
    return r;
}
__device__ __forceinline__ float2 up2(unsigned long long v) {
    float2 r;
    asm("mov.b64 {%0, %1}, %2;" : "=f"(r.x), "=f"(r.y) : "l"(v));
    return r;
}
__device__ __forceinline__ void fma2(unsigned long long& acc,
                                     unsigned long long a, unsigned long long b) {
    asm("fma.rn.f32x2 %0, %1, %2, %0;" : "+l"(acc) : "l"(a), "l"(b));
}

// ---------------- grid barrier (all NB blocks co-resident) ----------------
__device__ __forceinline__ void gridbar(int b) {
    __syncthreads();
    if (threadIdx.x == 0) {
        volatile unsigned* vg = (volatile unsigned*)&g_gen[b];
        unsigned snap = *vg;
        __threadfence();
        unsigned old = atomicAdd(&g_cnt[b], 1u);
        if (old == NB - 1) {
            g_cnt[b] = 0;
            __threadfence();
            atomicAdd(&g_gen[b], 1u);
        } else {
            while (*vg == snap) {}
        }
        __threadfence();
    }
    __syncthreads();
}

// ---------------- fused layer phase: 113-node tiles (128-row GEMM), 512 thr ----
// MEANSUM: additionally accumulate column sums of the stored output into
// g_meansum (used for layer 3; replaces a full re-read pass).
template <int FOUT, bool RELU, bool MEANSUM>
__device__ void layer_phase(
    const float* __restrict__ x,
    const float* __restrict__ Wl, const float* __restrict__ bias_p,
    const float* __restrict__ Wr, float* __restrict__ out,
    float* sWl, float* sWr, float (*sA)[64], float (*sX)[64], float* sPart)
{
    const int tid = threadIdx.x;
    const int lane = tid & 31;
    const int wid = tid >> 5;      // 0..15
    const int half = lane >> 4;    // 0/1
    const int lcol = lane & 15;

    // stage weights once per phase
    {
        const float4* Wl4 = (const float4*)Wl;
        const float4* Wr4 = (const float4*)Wr;
        for (int i = tid; i < 64 * FOUT / 4; i += TPB) {
            ((float4*)sWl)[i] = Wl4[i];
            ((float4*)sWr)[i] = Wr4[i];
        }
    }
    if (MEANSUM && tid < F3) sPart[tid] = 0.f;
    __syncthreads();

    const int CG = FOUT / 4;        // threads per node (16 or 8)
    const int NT = TPB / CG;        // node groups (32 or 64)
    const int TM = 128 / NT;        // nodes per thread (4 or 2)
    const int colg = tid % CG;
    const int nodeb = (tid / CG) * TM;
    const float4* __restrict__ x4 = (const float4*)x;

    float4 msum = make_float4(0.f, 0.f, 0.f, 0.f);

    for (int t = 0; t < TPB3; t++) {
        const int tile0 = (blockIdx.x * TPB3 + t) * TILEN;
        const int nval = (NN - tile0 < TILEN) ? (NN - tile0) : TILEN;
        if (nval <= 0) continue;   // uniform per block

        // ---- aggregate into sA: warp owns 8 node slots; half-warp split ----
#pragma unroll
        for (int j = 0; j < 8; j++) {
            int nl = wid * 8 + j;
            if (nl >= nval) break;
            int n = tile0 + nl;
            int d = g_cursor[n];
            int dc = d < PSTRIDE ? d : PSTRIDE;
            const int* __restrict__ cb = &g_colp[n * PSTRIDE];
            float4 a4 = make_float4(0.f, 0.f, 0.f, 0.f);
            int c = 0;
            for (; c + 8 <= dc; c += 8) {
                int4 s4 = __ldg((const int4*)&cb[c + half * 4]);
                float4 v0 = __ldg(&x4[s4.x * 16 + lcol]);
                float4 v1 = __ldg(&x4[s4.y * 16 + lcol]);
                float4 v2 = __ldg(&x4[s4.z * 16 + lcol]);
                float4 v3 = __ldg(&x4[s4.w * 16 + lcol]);
                a4.x += v0.x + v1.x + v2.x + v3.x;
                a4.y += v0.y + v1.y + v2.y + v3.y;
                a4.z += v0.z + v1.z + v2.z + v3.z;
                a4.w += v0.w + v1.w + v2.w + v3.w;
            }
            for (int e = c + half; e < dc; e += 2) {
                int s = __ldg(&cb[e]);
                float4 v = __ldg(&x4[s * 16 + lcol]);
                a4.x += v.x; a4.y += v.y; a4.z += v.z; a4.w += v.w;
            }
            a4.x += __shfl_xor_sync(0xffffffffu, a4.x, 16);
            a4.y += __shfl_xor_sync(0xffffffffu, a4.y, 16);
            a4.z += __shfl_xor_sync(0xffffffffu, a4.z, 16);
            a4.w += __shfl_xor_sync(0xffffffffu, a4.w, 16);
            float inv = 1.0f / fmaxf((float)d, 1.0f);
            if (half == 0) {
                a4.x *= inv; a4.y *= inv; a4.z *= inv; a4.w *= inv;
                ((float4*)&sA[nl][0])[lcol] = a4;
            }
        }
        // ---- load X tile into sX (valid rows only) ----
        {
            const float4* X4 = (const float4*)(x + tile0 * 64);
            for (int i = tid; i < nval * 16; i += TPB)
                ((float4*)&sX[0][0])[i] = X4[i];
        }
        __syncthreads();

        // ---- merged dual GEMM (FFMA2): acc = bias + agg@Wl + x@Wr ----
        unsigned long long acc01[TM], acc23[TM];
        {
            float4 bv = __ldg((const float4*)&bias_p[colg * 4]);
            unsigned long long b01 = pk2(bv.x, bv.y);
            unsigned long long b23 = pk2(bv.z, bv.w);
#pragma unroll
            for (int m = 0; m < TM; m++) { acc01[m] = b01; acc23[m] = b23; }
        }
#pragma unroll
        for (int k4 = 0; k4 < 16; k4++) {
            float4 av[TM], xv[TM];
#pragma unroll
            for (int m = 0; m < TM; m++) {
                av[m] = *(const float4*)&sA[nodeb + m][k4 * 4];
                xv[m] = *(const float4*)&sX[nodeb + m][k4 * 4];
            }
#pragma unroll
            for (int kk = 0; kk < 4; kk++) {
                ulonglong2 wl2 = *(const ulonglong2*)&sWl[(k4 * 4 + kk) * FOUT + colg * 4];
                ulonglong2 wr2 = *(const ulonglong2*)&sWr[(k4 * 4 + kk) * FOUT + colg * 4];
#pragma unroll
                for (int m = 0; m < TM; m++) {
                    float a = (kk == 0) ? av[m].x : (kk == 1) ? av[m].y : (kk == 2) ? av[m].z : av[m].w;
                    float xx = (kk == 0) ? xv[m].x : (kk == 1) ? xv[m].y : (kk == 2) ? xv[m].z : xv[m].w;
                    unsigned long long aa = pk2(a, a);
                    unsigned long long xp = pk2(xx, xx);
                    fma2(acc01[m], aa, wl2.x);
                    fma2(acc23[m], aa, wl2.y);
                    fma2(acc01[m], xp, wr2.x);
                    fma2(acc23[m], xp, wr2.y);
                }
            }
        }

        // ---- L2 norm (+relu), store; optional column-sum accumulation ----
#pragma unroll
        for (int m = 0; m < TM; m++) {
            float2 v01 = up2(acc01[m]);
            float2 v23 = up2(acc23[m]);
            float ss = v01.x * v01.x + v01.y * v01.y + v23.x * v23.x + v23.y * v23.y;
#pragma unroll
            for (int o = CG >> 1; o > 0; o >>= 1)
                ss += __shfl_xor_sync(0xffffffffu, ss, o);
            float inv = 1.0f / fmaxf(sqrtf(ss), 1e-12f);
            float4 v;
            v.x = v01.x * inv; v.y = v01.y * inv;
            v.z = v23.x * inv; v.w = v23.y * inv;
            if (RELU) {
                v.x = fmaxf(v.x, 0.f); v.y = fmaxf(v.y, 0.f);
                v.z = fmaxf(v.z, 0.f); v.w = fmaxf(v.w, 0.f);
            }
            int nl = nodeb + m;
            if (nl < nval) {
                *(float4*)&out[(tile0 + nl) * FOUT + colg * 4] = v;
                if (MEANSUM) {
                    msum.x += v.x; msum.y += v.y;
                    msum.z += v.z; msum.w += v.w;
                }
            }
        }
        __syncthreads();   // protect sA/sX before next tile
    }

    if (MEANSUM) {
        atomicAdd(&sPart[colg * 4 + 0], msum.x);
        atomicAdd(&sPart[colg * 4 + 1], msum.y);
        atomicAdd(&sPart[colg * 4 + 2], msum.z);
        atomicAdd(&sPart[colg * 4 + 3], msum.w);
        __syncthreads();
        if (tid < F3) atomicAdd(&g_meansum[tid], sPart[tid]);
    }
}

// ---------------- the single persistent kernel ----------------
__global__ void __launch_bounds__(TPB, 2) k_all(
    const float* __restrict__ feats, const void* __restrict__ edges,
    const float* __restrict__ W1l, const float* __restrict__ b1, const float* __restrict__ W1r,
    const float* __restrict__ W2l, const float* __restrict__ b2, const float* __restrict__ W2r,
    const float* __restrict__ W3l, const float* __restrict__ b3, const float* __restrict__ W3r,
    const float* __restrict__ Watt,
    const float* __restrict__ Wfc, const float* __restrict__ bfc,
    const float* __restrict__ Ws,  const float* __restrict__ bs,
    float* __restrict__ out)
{
    __shared__ float sWl[64 * 64];
    __shared__ float sWr[64 * 64];
    __shared__ float sA[128][64];
    __shared__ float sX[128][64];
    __shared__ float sPart[F3];
    __shared__ int s_any;

    const int tid = threadIdx.x;
    const int bid = blockIdx.x;
    const int gtid = bid * TPB + tid;
    const int lane = tid & 31;
    const int wid = tid >> 5;

    // ---- phase A: zero scratch ----
    for (int i = gtid; i < NN; i += NTH) g_cursor[i] = 0;
    if (gtid < F3) { g_meansum[gtid] = 0.f; g_pooled[gtid] = 0.f; }
    gridbar(0);

    // ---- phase B: CSR build ----
    {
        if (tid == 0) s_any = 0;
        __syncthreads();
        const unsigned* w = (const unsigned*)edges;
        if (tid < 256 && w[2 * tid + 1] != 0u) atomicOr(&s_any, 1);
        __syncthreads();
        const bool is64 = (s_any == 0);
        for (int i = gtid; i < NE; i += NTH) {
            int s, t;
            if (is64) {
                s = (int)((const long long*)edges)[i];
                t = (int)((const long long*)edges)[NE + i];
            } else {
                s = ((const int*)edges)[i];
                t = ((const int*)edges)[NE + i];
            }
            int pos = atomicAdd(&g_cursor[t], 1);
            if (pos < PSTRIDE) g_colp[t * PSTRIDE + pos] = s;
        }
    }
    gridbar(1);

    // ---- phases C/D/E: three fused layers (layer 3 folds in mean-sum) ----
    layer_phase<64, true,  false>(feats, W1l, b1, W1r, g_h0, sWl, sWr, sA, sX, sPart);
    gridbar(2);
    layer_phase<64, true,  false>(g_h0,  W2l, b2, W2r, g_h1, sWl, sWr, sA, sX, sPart);
    gridbar(3);
    layer_phase<32, false, true >(g_h1,  W3l, b3, W3r, g_h0, sWl, sWr, sA, sX, sPart);
    gridbar(4);

    const float* __restrict__ h3 = g_h0;   // [NN, 32]

    // ---- phase G: context = tanh(mean @ Watt) (block 0, warp 0) ----
    if (bid == 0 && wid == 0) {
        float s = 0.f;
        const float invN = 1.0f / (float)NN;
        for (int k = 0; k < F3; k++)
            s += (g_meansum[k] * invN) * __ldg(&Watt[k * F3 + lane]);
        g_ctx[lane] = tanhf(s);
    }
    gridbar(5);

    // ---- phase H: attention pooling ----
    {
        if (tid < F3) sPart[tid] = 0.f;
        __syncthreads();
        float ctx = g_ctx[lane];
        float acc = 0.f;
        int gw = bid * 16 + wid;
        for (int n = gw; n < NN; n += NB * 16) {
            float v = h3[n * F3 + lane];
            float d = v * ctx;
#pragma unroll
            for (int o = 16; o > 0; o >>= 1) d += __shfl_xor_sync(0xffffffffu, d, o);
            float att = 1.0f / (1.0f + expf(-d));
            acc += att * v;
        }
        atomicAdd(&sPart[lane], acc);
        __syncthreads();
        if (tid < F3) atomicAdd(&g_pooled[tid], sPart[tid]);
    }
    gridbar(6);

    // ---- phase I: final MLP (block 0) ----
    if (bid == 0 && wid == 0) {
        float hid = 0.f;
        if (lane < 16) {
            float s = __ldg(&bfc[lane]);
            for (int j = 0; j < F3; j++) s += g_pooled[j] * __ldg(&Wfc[j * 16 + lane]);
            hid = fmaxf(s, 0.f);
        }
        float term = (lane < 16) ? hid * __ldg(&Ws[lane]) : 0.f;
#pragma unroll
        for (int o = 16; o > 0; o >>= 1) term += __shfl_xor_sync(0xffffffffu, term, o);
        if (lane == 0) out[0] = 1.0f / (1.0f + expf(-(term + __ldg(&bs[0]))));
    }
}

// ---------------- launch ----------------
extern "C" void kernel_launch(void* const* d_in, const int* in_sizes, int n_in,
                              void* d_out, int out_size) {
    const float* feats = (const float*)d_in[0];
    const void*  edges = d_in[1];
    const float* W1l = (const float*)d_in[2];
    const float* b1  = (const float*)d_in[3];
    const float* W1r = (const float*)d_in[4];
    const float* W2l = (const float*)d_in[5];
    const float* b2  = (const float*)d_in[6];
    const float* W2r = (const float*)d_in[7];
    const float* W3l = (const float*)d_in[8];
    const float* b3  = (const float*)d_in[9];
    const float* W3r = (const float*)d_in[10];
    const float* Watt= (const float*)d_in[11];
    const float* Wfc = (const float*)d_in[12];
    const float* bfc = (const float*)d_in[13];
    const float* Ws  = (const float*)d_in[14];
    const float* bs  = (const float*)d_in[15];
    float* out = (float*)d_out;

    k_all<<<NB, TPB>>>(feats, edges,
                       W1l, b1, W1r, W2l, b2, W2r, W3l, b3, W3r,
                       Watt, Wfc, bfc, Ws, bs, out);
}

// round 16
// speedup vs baseline: 1.2801x; 1.0479x over previous
#include <cuda_runtime.h>
#include <cuda_fp16.h>
#include <math.h>

#define NN 100000
#define NE 1600000
#define F3 32
#define PSTRIDE 96          // padded CSR stride; Poisson(16) degrees
#define NB 296              // co-resident blocks (2/SM x 148 min-SM-count)
#define TPB 512
#define NTH (NB * TPB)
#define TILEN 113           // 296 blocks x 3 tiles x 113 = 100344 >= NN
#define TPB3 3              // tiles per block (exact)

// ---------------- scratch ----------------
__device__ unsigned g_fh[NN * 32];    // half2 feats
__device__ unsigned g_h0h[NN * 32];   // half2 layer1 out
__device__ unsigned g_h1h[NN * 32];   // half2 layer2 out
__device__ float    g_h3[NN * 32];    // fp32 layer3 out
__device__ int   g_cursor[NN];
__device__ int   g_colp[NN * PSTRIDE];
__device__ float g_meansum[F3];
__device__ float g_ctx[F3];
__device__ float g_pooled[F3];
__device__ unsigned g_cnt[16];
__device__ unsigned g_gen[16];

// ---------------- f32x2 / half2 helpers ----------------
__device__ __forceinline__ unsigned long long pk2(float lo, float hi) {
    unsigned long long r;
    asm("mov.b64 %0, {%1, %2};" : "=l"(r) : "f"(lo), "f"(hi));
    return r;
}
__device__ __forceinline__ float2 up2(unsigned long long v) {
    float2 r;
    asm("mov.b64 {%0, %1}, %2;" : "=f"(r.x), "=f"(r.y) : "l"(v));
    return r;
}
__device__ __forceinline__ void fma2(unsigned long long& acc,
                                     unsigned long long a, unsigned long long b) {
    asm("fma.rn.f32x2 %0, %1, %2, %0;" : "+l"(acc) : "l"(a), "l"(b));
}
__device__ __forceinline__ unsigned hadd2u(unsigned a, unsigned b) {
    __half2 r = __hadd2(*(__half2*)&a, *(__half2*)&b);
    return *(unsigned*)&r;
}
__device__ __forceinline__ float2 h2f2(unsigned a) {
    return __half22float2(*(__half2*)&a);
}
__device__ __forceinline__ unsigned f2h2(float a, float b) {
    __half2 p = __floats2half2_rn(a, b);
    return *(unsigned*)&p;
}

// ---------------- grid barrier ----------------
__device__ __forceinline__ void gridbar(int b) {
    __syncthreads();
    if (threadIdx.x == 0) {
        volatile unsigned* vg = (volatile unsigned*)&g_gen[b];
        unsigned snap = *vg;
        __threadfence();
        unsigned old = atomicAdd(&g_cnt[b], 1u);
        if (old == NB - 1) {
            g_cnt[b] = 0;
            __threadfence();
            atomicAdd(&g_gen[b], 1u);
        } else {
            while (*vg == snap) {}
        }
        __threadfence();
    }
    __syncthreads();
}

// ---------------- fused layer phase: half2 gather, fp32 FFMA2 GEMM ----------
// xh: half2 input rows (32 u32 per node). Gather accumulates in half2.
// HALFOUT: store output as half2 to outh; else fp32 to outf (+ MEANSUM).
template <int FOUT, bool RELU, bool MEANSUM, bool HALFOUT>
__device__ void layer_phase(
    const unsigned* __restrict__ xh,
    const float* __restrict__ Wl, const float* __restrict__ bias_p,
    const float* __restrict__ Wr,
    unsigned* __restrict__ outh, float* __restrict__ outf,
    float* sWl, float* sWr, float (*sA)[64], float (*sX)[64], float* sPart)
{
    const int tid = threadIdx.x;
    const int lane = tid & 31;
    const int wid = tid >> 5;      // 0..15
    const int half_ = lane >> 4;   // 0/1
    const int lcol = lane & 15;

    // stage weights once per phase
    {
        const float4* Wl4 = (const float4*)Wl;
        const float4* Wr4 = (const float4*)Wr;
        for (int i = tid; i < 64 * FOUT / 4; i += TPB) {
            ((float4*)sWl)[i] = Wl4[i];
            ((float4*)sWr)[i] = Wr4[i];
        }
    }
    if (MEANSUM && tid < F3) sPart[tid] = 0.f;
    __syncthreads();

    const int CG = FOUT / 4;        // threads per node (16 or 8)
    const int NT = TPB / CG;        // node groups
    const int TM = 128 / NT;        // nodes per thread (4 or 2)
    const int colg = tid % CG;
    const int nodeb = (tid / CG) * TM;
    const uint2* __restrict__ xh2 = (const uint2*)xh;   // row = 16 uint2

    float4 msum = make_float4(0.f, 0.f, 0.f, 0.f);

    for (int t = 0; t < TPB3; t++) {
        const int tile0 = (blockIdx.x * TPB3 + t) * TILEN;
        const int nval = (NN - tile0 < TILEN) ? (NN - tile0) : TILEN;
        if (nval <= 0) continue;

        // ---- aggregate into sA: warp owns 8 nodes; half-warp split edges ----
        // half2 rows: 128B -> 1 L1 wavefront/edge; accumulate with HADD2.
#pragma unroll
        for (int j = 0; j < 8; j++) {
            int nl = wid * 8 + j;
            if (nl >= nval) break;
            int n = tile0 + nl;
            int d = g_cursor[n];
            int dc = d < PSTRIDE ? d : PSTRIDE;
            const int* __restrict__ cb = &g_colp[n * PSTRIDE];
            unsigned acc0 = 0u, acc1 = 0u;  // two half2 accumulators (4 halves)
            int c = 0;
            for (; c + 8 <= dc; c += 8) {
                int4 s4 = __ldg((const int4*)&cb[c + half_ * 4]);
                uint2 q0 = __ldg(&xh2[s4.x * 16 + lcol]);
                uint2 q1 = __ldg(&xh2[s4.y * 16 + lcol]);
                uint2 q2 = __ldg(&xh2[s4.z * 16 + lcol]);
                uint2 q3 = __ldg(&xh2[s4.w * 16 + lcol]);
                acc0 = hadd2u(acc0, hadd2u(hadd2u(q0.x, q1.x), hadd2u(q2.x, q3.x)));
                acc1 = hadd2u(acc1, hadd2u(hadd2u(q0.y, q1.y), hadd2u(q2.y, q3.y)));
            }
            for (int e = c + half_; e < dc; e += 2) {
                uint2 q = __ldg(&xh2[__ldg(&cb[e]) * 16 + lcol]);
                acc0 = hadd2u(acc0, q.x);
                acc1 = hadd2u(acc1, q.y);
            }
            // combine halves (lane <-> lane^16, same lcol)
            acc0 = hadd2u(acc0, __shfl_xor_sync(0xffffffffu, acc0, 16));
            acc1 = hadd2u(acc1, __shfl_xor_sync(0xffffffffu, acc1, 16));
            if (half_ == 0) {
                float inv = 1.0f / fmaxf((float)d, 1.0f);
                float2 f0 = h2f2(acc0);
                float2 f1 = h2f2(acc1);
                float4 a4;
                a4.x = f0.x * inv; a4.y = f0.y * inv;
                a4.z = f1.x * inv; a4.w = f1.y * inv;
                ((float4*)&sA[nl][0])[lcol] = a4;
            }
        }
        // ---- load X tile into sX (half -> fp32) ----
        {
            const uint2* Xh = xh2 + tile0 * 16;
            for (int i = tid; i < nval * 16; i += TPB) {
                uint2 q = __ldg(&Xh[i]);
                float2 f0 = h2f2(q.x);
                float2 f1 = h2f2(q.y);
                ((float4*)&sX[0][0])[i] = make_float4(f0.x, f0.y, f1.x, f1.y);
            }
        }
        __syncthreads();

        // ---- merged dual GEMM (FFMA2): acc = bias + agg@Wl + x@Wr ----
        unsigned long long acc01[TM], acc23[TM];
        {
            float4 bv = __ldg((const float4*)&bias_p[colg * 4]);
            unsigned long long b01 = pk2(bv.x, bv.y);
            unsigned long long b23 = pk2(bv.z, bv.w);
#pragma unroll
            for (int m = 0; m < TM; m++) { acc01[m] = b01; acc23[m] = b23; }
        }
#pragma unroll
        for (int k4 = 0; k4 < 16; k4++) {
            float4 av[TM], xv[TM];
#pragma unroll
            for (int m = 0; m < TM; m++) {
                av[m] = *(const float4*)&sA[nodeb + m][k4 * 4];
                xv[m] = *(const float4*)&sX[nodeb + m][k4 * 4];
            }
#pragma unroll
            for (int kk = 0; kk < 4; kk++) {
                ulonglong2 wl2 = *(const ulonglong2*)&sWl[(k4 * 4 + kk) * FOUT + colg * 4];
                ulonglong2 wr2 = *(const ulonglong2*)&sWr[(k4 * 4 + kk) * FOUT + colg * 4];
#pragma unroll
                for (int m = 0; m < TM; m++) {
                    float a = (kk == 0) ? av[m].x : (kk == 1) ? av[m].y : (kk == 2) ? av[m].z : av[m].w;
                    float xx = (kk == 0) ? xv[m].x : (kk == 1) ? xv[m].y : (kk == 2) ? xv[m].z : xv[m].w;
                    unsigned long long aa = pk2(a, a);
                    unsigned long long xp = pk2(xx, xx);
                    fma2(acc01[m], aa, wl2.x);
                    fma2(acc23[m], aa, wl2.y);
                    fma2(acc01[m], xp, wr2.x);
                    fma2(acc23[m], xp, wr2.y);
                }
            }
        }

        // ---- L2 norm (+relu), store half2 or fp32; optional meansum ----
#pragma unroll
        for (int m = 0; m < TM; m++) {
            float2 v01 = up2(acc01[m]);
            float2 v23 = up2(acc23[m]);
            float ss = v01.x * v01.x + v01.y * v01.y + v23.x * v23.x + v23.y * v23.y;
#pragma unroll
            for (int o = CG >> 1; o > 0; o >>= 1)
                ss += __shfl_xor_sync(0xffffffffu, ss, o);
            float inv = 1.0f / fmaxf(sqrtf(ss), 1e-12f);
            float4 v;
            v.x = v01.x * inv; v.y = v01.y * inv;
            v.z = v23.x * inv; v.w = v23.y * inv;
            if (RELU) {
                v.x = fmaxf(v.x, 0.f); v.y = fmaxf(v.y, 0.f);
                v.z = fmaxf(v.z, 0.f); v.w = fmaxf(v.w, 0.f);
            }
            int nl = nodeb + m;
            if (nl < nval) {
                if (HALFOUT) {
                    uint2 p;
                    p.x = f2h2(v.x, v.y);
                    p.y = f2h2(v.z, v.w);
                    *(uint2*)&outh[(tile0 + nl) * (FOUT / 2) + colg * 2] = p;
                } else {
                    *(float4*)&outf[(tile0 + nl) * FOUT + colg * 4] = v;
                }
                if (MEANSUM) {
                    msum.x += v.x; msum.y += v.y;
                    msum.z += v.z; msum.w += v.w;
                }
            }
        }
        __syncthreads();   // protect sA/sX before next tile
    }

    if (MEANSUM) {
        atomicAdd(&sPart[colg * 4 + 0], msum.x);
        atomicAdd(&sPart[colg * 4 + 1], msum.y);
        atomicAdd(&sPart[colg * 4 + 2], msum.z);
        atomicAdd(&sPart[colg * 4 + 3], msum.w);
        __syncthreads();
        if (tid < F3) atomicAdd(&g_meansum[tid], sPart[tid]);
    }
}

// ---------------- the single persistent kernel ----------------
__global__ void __launch_bounds__(TPB, 2) k_all(
    const float* __restrict__ feats, const void* __restrict__ edges,
    const float* __restrict__ W1l, const float* __restrict__ b1, const float* __restrict__ W1r,
    const float* __restrict__ W2l, const float* __restrict__ b2, const float* __restrict__ W2r,
    const float* __restrict__ W3l, const float* __restrict__ b3, const float* __restrict__ W3r,
    const float* __restrict__ Watt,
    const float* __restrict__ Wfc, const float* __restrict__ bfc,
    const float* __restrict__ Ws,  const float* __restrict__ bs,
    float* __restrict__ out)
{
    __shared__ float sWl[64 * 64];
    __shared__ float sWr[64 * 64];
    __shared__ float sA[128][64];
    __shared__ float sX[128][64];
    __shared__ float sPart[F3];
    __shared__ int s_any;

    const int tid = threadIdx.x;
    const int bid = blockIdx.x;
    const int gtid = bid * TPB + tid;
    const int lane = tid & 31;
    const int wid = tid >> 5;

    // ---- phase A: zero scratch + convert feats -> half2 ----
    for (int i = gtid; i < NN; i += NTH) g_cursor[i] = 0;
    if (gtid < F3) { g_meansum[gtid] = 0.f; g_pooled[gtid] = 0.f; }
    {
        const float4* f4 = (const float4*)feats;
        uint2* fh2 = (uint2*)g_fh;
        for (int i = gtid; i < NN * 16; i += NTH) {
            float4 f = __ldg(&f4[i]);
            uint2 p;
            p.x = f2h2(f.x, f.y);
            p.y = f2h2(f.z, f.w);
            fh2[i] = p;
        }
    }
    gridbar(0);

    // ---- phase B: CSR build ----
    {
        if (tid == 0) s_any = 0;
        __syncthreads();
        const unsigned* w = (const unsigned*)edges;
        if (tid < 256 && w[2 * tid + 1] != 0u) atomicOr(&s_any, 1);
        __syncthreads();
        const bool is64 = (s_any == 0);
        for (int i = gtid; i < NE; i += NTH) {
            int s, t;
            if (is64) {
                s = (int)((const long long*)edges)[i];
                t = (int)((const long long*)edges)[NE + i];
            } else {
                s = ((const int*)edges)[i];
                t = ((const int*)edges)[NE + i];
            }
            int pos = atomicAdd(&g_cursor[t], 1);
            if (pos < PSTRIDE) g_colp[t * PSTRIDE + pos] = s;
        }
    }
    gridbar(1);

    // ---- phases C/D/E: three fused layers (layer 3 folds in mean-sum) ----
    layer_phase<64, true,  false, true >(g_fh,  W1l, b1, W1r, g_h0h, (float*)0, sWl, sWr, sA, sX, sPart);
    gridbar(2);
    layer_phase<64, true,  false, true >(g_h0h, W2l, b2, W2r, g_h1h, (float*)0, sWl, sWr, sA, sX, sPart);
    gridbar(3);
    layer_phase<32, false, true,  false>(g_h1h, W3l, b3, W3r, (unsigned*)0, g_h3, sWl, sWr, sA, sX, sPart);
    gridbar(4);

    const float* __restrict__ h3 = g_h3;   // [NN, 32] fp32

    // ---- phase G: context = tanh(mean @ Watt) (block 0, warp 0) ----
    if (bid == 0 && wid == 0) {
        float s = 0.f;
        const float invN = 1.0f / (float)NN;
        for (int k = 0; k < F3; k++)
            s += (g_meansum[k] * invN) * __ldg(&Watt[k * F3 + lane]);
        g_ctx[lane] = tanhf(s);
    }
    gridbar(5);

    // ---- phase H: attention pooling ----
    {
        if (tid < F3) sPart[tid] = 0.f;
        __syncthreads();
        float ctx = g_ctx[lane];
        float acc = 0.f;
        int gw = bid * 16 + wid;
        for (int n = gw; n < NN; n += NB * 16) {
            float v = h3[n * F3 + lane];
            float d = v * ctx;
#pragma unroll
            for (int o = 16; o > 0; o >>= 1) d += __shfl_xor_sync(0xffffffffu, d, o);
            float att = 1.0f / (1.0f + expf(-d));
            acc += att * v;
        }
        atomicAdd(&sPart[lane], acc);
        __syncthreads();
        if (tid < F3) atomicAdd(&g_pooled[tid], sPart[tid]);
    }
    gridbar(6);

    // ---- phase I: final MLP (block 0) ----
    if (bid == 0 && wid == 0) {
        float hid = 0.f;
        if (lane < 16) {
            float s = __ldg(&bfc[lane]);
            for (int j = 0; j < F3; j++) s += g_pooled[j] * __ldg(&Wfc[j * 16 + lane]);
            hid = fmaxf(s, 0.f);
        }
        float term = (lane < 16) ? hid * __ldg(&Ws[lane]) : 0.f;
#pragma unroll
        for (int o = 16; o > 0; o >>= 1) term += __shfl_xor_sync(0xffffffffu, term, o);
        if (lane == 0) out[0] = 1.0f / (1.0f + expf(-(term + __ldg(&bs[0]))));
    }
}

// ---------------- launch ----------------
extern "C" void kernel_launch(void* const* d_in, const int* in_sizes, int n_in,
                              void* d_out, int out_size) {
    const float* feats = (const float*)d_in[0];
    const void*  edges = d_in[1];
    const float* W1l = (const float*)d_in[2];
    const float* b1  = (const float*)d_in[3];
    const float* W1r = (const float*)d_in[4];
    const float* W2l = (const float*)d_in[5];
    const float* b2  = (const float*)d_in[6];
    const float* W2r = (const float*)d_in[7];
    const float* W3l = (const float*)d_in[8];
    const float* b3  = (const float*)d_in[9];
    const float* W3r = (const float*)d_in[10];
    const float* Watt= (const float*)d_in[11];
    const float* Wfc = (const float*)d_in[12];
    const float* bfc = (const float*)d_in[13];
    const float* Ws  = (const float*)d_in[14];
    const float* bs  = (const float*)d_in[15];
    float* out = (float*)d_out;

    k_all<<<NB, TPB>>>(feats, edges,
                       W1l, b1, W1r, W2l, b2, W2r, W3l, b3, W3r,
                       Watt, Wfc, bfc, Ws, bs, out);
}

// round 17
// speedup vs baseline: 1.3284x; 1.0377x over previous
#include <cuda_runtime.h>
#include <cuda_fp16.h>
#include <math.h>

#define NN 100000
#define NE 1600000
#define F3 32
#define PSTRIDE 96          // padded CSR stride; Poisson(16) degrees
#define NB 296              // co-resident blocks (2/SM x 148 min-SM-count)
#define TPB 512
#define NTH (NB * TPB)
#define TILEN 113           // 296 blocks x 3 tiles x 113 = 100344 >= NN
#define TPB3 3              // tiles per block (exact)

// ---------------- scratch ----------------
__device__ unsigned g_fh[NN * 32];    // half2 feats
__device__ unsigned g_h0h[NN * 32];   // half2 layer1 out
__device__ unsigned g_h1h[NN * 32];   // half2 layer2 out
__device__ float    g_h3[NN * 32];    // fp32 layer3 out
__device__ int   g_cursor[NN];
__device__ int   g_colp[NN * PSTRIDE];
__device__ float g_meansum[F3];
__device__ float g_ctx[F3];
__device__ float g_pooled[F3];
__device__ unsigned g_cnt[16];
__device__ unsigned g_gen[16];

// ---------------- f32x2 / half2 helpers ----------------
__device__ __forceinline__ unsigned long long pk2(float lo, float hi) {
    unsigned long long r;
    asm("mov.b64 %0, {%1, %2};" : "=l"(r) : "f"(lo), "f"(hi));
    return r;
}
__device__ __forceinline__ float2 up2(unsigned long long v) {
    float2 r;
    asm("mov.b64 {%0, %1}, %2;" : "=f"(r.x), "=f"(r.y) : "l"(v));
    return r;
}
__device__ __forceinline__ void fma2(unsigned long long& acc,
                                     unsigned long long a, unsigned long long b) {
    asm("fma.rn.f32x2 %0, %1, %2, %0;" : "+l"(acc) : "l"(a), "l"(b));
}
__device__ __forceinline__ unsigned hadd2u(unsigned a, unsigned b) {
    __half2 r = __hadd2(*(__half2*)&a, *(__half2*)&b);
    return *(unsigned*)&r;
}
__device__ __forceinline__ float2 h2f2(unsigned a) {
    return __half22float2(*(__half2*)&a);
}
__device__ __forceinline__ unsigned f2h2(float a, float b) {
    __half2 p = __floats2half2_rn(a, b);
    return *(unsigned*)&p;
}

// ---------------- grid barrier ----------------
__device__ __forceinline__ void gridbar(int b) {
    __syncthreads();
    if (threadIdx.x == 0) {
        volatile unsigned* vg = (volatile unsigned*)&g_gen[b];
        unsigned snap = *vg;
        __threadfence();
        unsigned old = atomicAdd(&g_cnt[b], 1u);
        if (old == NB - 1) {
            g_cnt[b] = 0;
            __threadfence();
            atomicAdd(&g_gen[b], 1u);
        } else {
            while (*vg == snap) {}
        }
        __threadfence();
    }
    __syncthreads();
}

// drain one node's remaining edges (8-chunks then scalar tail)
__device__ __forceinline__ void drain_node(
    const uint2* __restrict__ xh2, const int* __restrict__ cb,
    int& c, int dc, unsigned& acc0, unsigned& acc1, int half_, int lcol)
{
    for (; c + 8 <= dc; c += 8) {
        int4 s4 = __ldg((const int4*)&cb[c + half_ * 4]);
        uint2 q0 = __ldg(&xh2[s4.x * 16 + lcol]);
        uint2 q1 = __ldg(&xh2[s4.y * 16 + lcol]);
        uint2 q2 = __ldg(&xh2[s4.z * 16 + lcol]);
        uint2 q3 = __ldg(&xh2[s4.w * 16 + lcol]);
        acc0 = hadd2u(acc0, hadd2u(hadd2u(q0.x, q1.x), hadd2u(q2.x, q3.x)));
        acc1 = hadd2u(acc1, hadd2u(hadd2u(q0.y, q1.y), hadd2u(q2.y, q3.y)));
    }
    for (int e = c + half_; e < dc; e += 2) {
        uint2 q = __ldg(&xh2[__ldg(&cb[e]) * 16 + lcol]);
        acc0 = hadd2u(acc0, q.x);
        acc1 = hadd2u(acc1, q.y);
    }
}

// ---------------- fused layer phase: half2 gather (node-pair interleaved) ----
template <int FOUT, bool RELU, bool MEANSUM, bool HALFOUT>
__device__ void layer_phase(
    const unsigned* __restrict__ xh,
    const float* __restrict__ Wl, const float* __restrict__ bias_p,
    const float* __restrict__ Wr,
    unsigned* __restrict__ outh, float* __restrict__ outf,
    float* sWl, float* sWr, float (*sA)[64], float (*sX)[64], float* sPart)
{
    const int tid = threadIdx.x;
    const int lane = tid & 31;
    const int wid = tid >> 5;      // 0..15
    const int half_ = lane >> 4;   // 0/1
    const int lcol = lane & 15;

    // stage weights once per phase
    {
        const float4* Wl4 = (const float4*)Wl;
        const float4* Wr4 = (const float4*)Wr;
        for (int i = tid; i < 64 * FOUT / 4; i += TPB) {
            ((float4*)sWl)[i] = Wl4[i];
            ((float4*)sWr)[i] = Wr4[i];
        }
    }
    if (MEANSUM && tid < F3) sPart[tid] = 0.f;
    __syncthreads();

    const int CG = FOUT / 4;        // threads per node (16 or 8)
    const int NT = TPB / CG;        // node groups
    const int TM = 128 / NT;        // nodes per thread (4 or 2)
    const int colg = tid % CG;
    const int nodeb = (tid / CG) * TM;
    const uint2* __restrict__ xh2 = (const uint2*)xh;   // row = 16 uint2

    float4 msum = make_float4(0.f, 0.f, 0.f, 0.f);

    for (int t = 0; t < TPB3; t++) {
        const int tile0 = (blockIdx.x * TPB3 + t) * TILEN;
        const int nval = (NN - tile0 < TILEN) ? (NN - tile0) : TILEN;
        if (nval <= 0) continue;

        // ---- aggregate: warp owns 8 nodes, processed in interleaved pairs ----
#pragma unroll
        for (int jp = 0; jp < 4; jp++) {
            int nl0 = wid * 8 + jp * 2;
            int nl1 = nl0 + 1;
            if (nl0 >= nval) break;
            bool ok1 = nl1 < nval;
            int n0 = tile0 + nl0;
            int n1 = tile0 + nl1;
            int d0 = g_cursor[n0];
            int d1 = ok1 ? g_cursor[n1] : 0;
            int dc0 = d0 < PSTRIDE ? d0 : PSTRIDE;
            int dc1 = d1 < PSTRIDE ? d1 : PSTRIDE;
            const int* __restrict__ cb0 = &g_colp[n0 * PSTRIDE];
            const int* __restrict__ cb1 = &g_colp[n1 * PSTRIDE];
            unsigned a00 = 0u, a01 = 0u;   // node0 accumulators
            unsigned a10 = 0u, a11 = 0u;   // node1 accumulators
            int c0 = 0, c1 = 0;
            // interleaved 8-edge chunks: 8 independent row loads in flight
            while (c0 + 8 <= dc0 && c1 + 8 <= dc1) {
                int4 s40 = __ldg((const int4*)&cb0[c0 + half_ * 4]);
                int4 s41 = __ldg((const int4*)&cb1[c1 + half_ * 4]);
                uint2 p0 = __ldg(&xh2[s40.x * 16 + lcol]);
                uint2 q0 = __ldg(&xh2[s41.x * 16 + lcol]);
                uint2 p1 = __ldg(&xh2[s40.y * 16 + lcol]);
                uint2 q1 = __ldg(&xh2[s41.y * 16 + lcol]);
                uint2 p2 = __ldg(&xh2[s40.z * 16 + lcol]);
                uint2 q2 = __ldg(&xh2[s41.z * 16 + lcol]);
                uint2 p3 = __ldg(&xh2[s40.w * 16 + lcol]);
                uint2 q3 = __ldg(&xh2[s41.w * 16 + lcol]);
                a00 = hadd2u(a00, hadd2u(hadd2u(p0.x, p1.x), hadd2u(p2.x, p3.x)));
                a01 = hadd2u(a01, hadd2u(hadd2u(p0.y, p1.y), hadd2u(p2.y, p3.y)));
                a10 = hadd2u(a10, hadd2u(hadd2u(q0.x, q1.x), hadd2u(q2.x, q3.x)));
                a11 = hadd2u(a11, hadd2u(hadd2u(q0.y, q1.y), hadd2u(q2.y, q3.y)));
                c0 += 8; c1 += 8;
            }
            drain_node(xh2, cb0, c0, dc0, a00, a01, half_, lcol);
            drain_node(xh2, cb1, c1, dc1, a10, a11, half_, lcol);
            // combine halves (lane <-> lane^16, same lcol)
            a00 = hadd2u(a00, __shfl_xor_sync(0xffffffffu, a00, 16));
            a01 = hadd2u(a01, __shfl_xor_sync(0xffffffffu, a01, 16));
            a10 = hadd2u(a10, __shfl_xor_sync(0xffffffffu, a10, 16));
            a11 = hadd2u(a11, __shfl_xor_sync(0xffffffffu, a11, 16));
            if (half_ == 0) {
                float inv0 = 1.0f / fmaxf((float)d0, 1.0f);
                float2 f0 = h2f2(a00), f1 = h2f2(a01);
                ((float4*)&sA[nl0][0])[lcol] =
                    make_float4(f0.x * inv0, f0.y * inv0, f1.x * inv0, f1.y * inv0);
                if (ok1) {
                    float inv1 = 1.0f / fmaxf((float)d1, 1.0f);
                    float2 g0 = h2f2(a10), g1 = h2f2(a11);
                    ((float4*)&sA[nl1][0])[lcol] =
                        make_float4(g0.x * inv1, g0.y * inv1, g1.x * inv1, g1.y * inv1);
                }
            }
        }
        // ---- load X tile into sX (half -> fp32) ----
        {
            const uint2* Xh = xh2 + tile0 * 16;
            for (int i = tid; i < nval * 16; i += TPB) {
                uint2 q = __ldg(&Xh[i]);
                float2 f0 = h2f2(q.x);
                float2 f1 = h2f2(q.y);
                ((float4*)&sX[0][0])[i] = make_float4(f0.x, f0.y, f1.x, f1.y);
            }
        }
        __syncthreads();

        // ---- merged dual GEMM (FFMA2): acc = bias + agg@Wl + x@Wr ----
        unsigned long long acc01[TM], acc23[TM];
        {
            float4 bv = __ldg((const float4*)&bias_p[colg * 4]);
            unsigned long long b01 = pk2(bv.x, bv.y);
            unsigned long long b23 = pk2(bv.z, bv.w);
#pragma unroll
            for (int m = 0; m < TM; m++) { acc01[m] = b01; acc23[m] = b23; }
        }
#pragma unroll
        for (int k4 = 0; k4 < 16; k4++) {
            float4 av[TM], xv[TM];
#pragma unroll
            for (int m = 0; m < TM; m++) {
                av[m] = *(const float4*)&sA[nodeb + m][k4 * 4];
                xv[m] = *(const float4*)&sX[nodeb + m][k4 * 4];
            }
#pragma unroll
            for (int kk = 0; kk < 4; kk++) {
                ulonglong2 wl2 = *(const ulonglong2*)&sWl[(k4 * 4 + kk) * FOUT + colg * 4];
                ulonglong2 wr2 = *(const ulonglong2*)&sWr[(k4 * 4 + kk) * FOUT + colg * 4];
#pragma unroll
                for (int m = 0; m < TM; m++) {
                    float a = (kk == 0) ? av[m].x : (kk == 1) ? av[m].y : (kk == 2) ? av[m].z : av[m].w;
                    float xx = (kk == 0) ? xv[m].x : (kk == 1) ? xv[m].y : (kk == 2) ? xv[m].z : xv[m].w;
                    unsigned long long aa = pk2(a, a);
                    unsigned long long xp = pk2(xx, xx);
                    fma2(acc01[m], aa, wl2.x);
                    fma2(acc23[m], aa, wl2.y);
                    fma2(acc01[m], xp, wr2.x);
                    fma2(acc23[m], xp, wr2.y);
                }
            }
        }

        // ---- L2 norm (+relu), store half2 or fp32; optional meansum ----
#pragma unroll
        for (int m = 0; m < TM; m++) {
            float2 v01 = up2(acc01[m]);
            float2 v23 = up2(acc23[m]);
            float ss = v01.x * v01.x + v01.y * v01.y + v23.x * v23.x + v23.y * v23.y;
#pragma unroll
            for (int o = CG >> 1; o > 0; o >>= 1)
                ss += __shfl_xor_sync(0xffffffffu, ss, o);
            float inv = 1.0f / fmaxf(sqrtf(ss), 1e-12f);
            float4 v;
            v.x = v01.x * inv; v.y = v01.y * inv;
            v.z = v23.x * inv; v.w = v23.y * inv;
            if (RELU) {
                v.x = fmaxf(v.x, 0.f); v.y = fmaxf(v.y, 0.f);
                v.z = fmaxf(v.z, 0.f); v.w = fmaxf(v.w, 0.f);
            }
            int nl = nodeb + m;
            if (nl < nval) {
                if (HALFOUT) {
                    uint2 p;
                    p.x = f2h2(v.x, v.y);
                    p.y = f2h2(v.z, v.w);
                    *(uint2*)&outh[(tile0 + nl) * (FOUT / 2) + colg * 2] = p;
                } else {
                    *(float4*)&outf[(tile0 + nl) * FOUT + colg * 4] = v;
                }
                if (MEANSUM) {
                    msum.x += v.x; msum.y += v.y;
                    msum.z += v.z; msum.w += v.w;
                }
            }
        }
        __syncthreads();   // protect sA/sX before next tile
    }

    if (MEANSUM) {
        atomicAdd(&sPart[colg * 4 + 0], msum.x);
        atomicAdd(&sPart[colg * 4 + 1], msum.y);
        atomicAdd(&sPart[colg * 4 + 2], msum.z);
        atomicAdd(&sPart[colg * 4 + 3], msum.w);
        __syncthreads();
        if (tid < F3) atomicAdd(&g_meansum[tid], sPart[tid]);
    }
}

// ---------------- the single persistent kernel ----------------
__global__ void __launch_bounds__(TPB, 2) k_all(
    const float* __restrict__ feats, const void* __restrict__ edges,
    const float* __restrict__ W1l, const float* __restrict__ b1, const float* __restrict__ W1r,
    const float* __restrict__ W2l, const float* __restrict__ b2, const float* __restrict__ W2r,
    const float* __restrict__ W3l, const float* __restrict__ b3, const float* __restrict__ W3r,
    const float* __restrict__ Watt,
    const float* __restrict__ Wfc, const float* __restrict__ bfc,
    const float* __restrict__ Ws,  const float* __restrict__ bs,
    float* __restrict__ out)
{
    __shared__ float sWl[64 * 64];
    __shared__ float sWr[64 * 64];
    __shared__ float sA[128][64];
    __shared__ float sX[128][64];
    __shared__ float sPart[F3];
    __shared__ int s_any;

    const int tid = threadIdx.x;
    const int bid = blockIdx.x;
    const int gtid = bid * TPB + tid;
    const int lane = tid & 31;
    const int wid = tid >> 5;

    // ---- phase A: zero scratch + convert feats -> half2 ----
    for (int i = gtid; i < NN; i += NTH) g_cursor[i] = 0;
    if (gtid < F3) { g_meansum[gtid] = 0.f; g_pooled[gtid] = 0.f; }
    {
        const float4* f4 = (const float4*)feats;
        uint2* fh2 = (uint2*)g_fh;
        for (int i = gtid; i < NN * 16; i += NTH) {
            float4 f = __ldg(&f4[i]);
            uint2 p;
            p.x = f2h2(f.x, f.y);
            p.y = f2h2(f.z, f.w);
            fh2[i] = p;
        }
    }
    gridbar(0);

    // ---- phase B: CSR build ----
    {
        if (tid == 0) s_any = 0;
        __syncthreads();
        const unsigned* w = (const unsigned*)edges;
        if (tid < 256 && w[2 * tid + 1] != 0u) atomicOr(&s_any, 1);
        __syncthreads();
        const bool is64 = (s_any == 0);
        for (int i = gtid; i < NE; i += NTH) {
            int s, t;
            if (is64) {
                s = (int)((const long long*)edges)[i];
                t = (int)((const long long*)edges)[NE + i];
            } else {
                s = ((const int*)edges)[i];
                t = ((const int*)edges)[NE + i];
            }
            int pos = atomicAdd(&g_cursor[t], 1);
            if (pos < PSTRIDE) g_colp[t * PSTRIDE + pos] = s;
        }
    }
    gridbar(1);

    // ---- phases C/D/E: three fused layers (layer 3 folds in mean-sum) ----
    layer_phase<64, true,  false, true >(g_fh,  W1l, b1, W1r, g_h0h, (float*)0, sWl, sWr, sA, sX, sPart);
    gridbar(2);
    layer_phase<64, true,  false, true >(g_h0h, W2l, b2, W2r, g_h1h, (float*)0, sWl, sWr, sA, sX, sPart);
    gridbar(3);
    layer_phase<32, false, true,  false>(g_h1h, W3l, b3, W3r, (unsigned*)0, g_h3, sWl, sWr, sA, sX, sPart);
    gridbar(4);

    const float* __restrict__ h3 = g_h3;   // [NN, 32] fp32

    // ---- phase G: context = tanh(mean @ Watt) (block 0, warp 0) ----
    if (bid == 0 && wid == 0) {
        float s = 0.f;
        const float invN = 1.0f / (float)NN;
        for (int k = 0; k < F3; k++)
            s += (g_meansum[k] * invN) * __ldg(&Watt[k * F3 + lane]);
        g_ctx[lane] = tanhf(s);
    }
    gridbar(5);

    // ---- phase H: attention pooling ----
    {
        if (tid < F3) sPart[tid] = 0.f;
        __syncthreads();
        float ctx = g_ctx[lane];
        float acc = 0.f;
        int gw = bid * 16 + wid;
        for (int n = gw; n < NN; n += NB * 16) {
            float v = h3[n * F3 + lane];
            float d = v * ctx;
#pragma unroll
            for (int o = 16; o > 0; o >>= 1) d += __shfl_xor_sync(0xffffffffu, d, o);
            float att = 1.0f / (1.0f + expf(-d));
            acc += att * v;
        }
        atomicAdd(&sPart[lane], acc);
        __syncthreads();
        if (tid < F3) atomicAdd(&g_pooled[tid], sPart[tid]);
    }
    gridbar(6);

    // ---- phase I: final MLP (block 0) ----
    if (bid == 0 && wid == 0) {
        float hid = 0.f;
        if (lane < 16) {
            float s = __ldg(&bfc[lane]);
            for (int j = 0; j < F3; j++) s += g_pooled[j] * __ldg(&Wfc[j * 16 + lane]);
            hid = fmaxf(s, 0.f);
        }
        float term = (lane < 16) ? hid * __ldg(&Ws[lane]) : 0.f;
#pragma unroll
        for (int o = 16; o > 0; o >>= 1) term += __shfl_xor_sync(0xffffffffu, term, o);
        if (lane == 0) out[0] = 1.0f / (1.0f + expf(-(term + __ldg(&bs[0]))));
    }
}

// ---------------- launch ----------------
extern "C" void kernel_launch(void* const* d_in, const int* in_sizes, int n_in,
                              void* d_out, int out_size) {
    const float* feats = (const float*)d_in[0];
    const void*  edges = d_in[1];
    const float* W1l = (const float*)d_in[2];
    const float* b1  = (const float*)d_in[3];
    const float* W1r = (const float*)d_in[4];
    const float* W2l = (const float*)d_in[5];
    const float* b2  = (const float*)d_in[6];
    const float* W2r = (const float*)d_in[7];
    const float* W3l = (const float*)d_in[8];
    const float* b3  = (const float*)d_in[9];
    const float* W3r = (const float*)d_in[10];
    const float* Watt= (const float*)d_in[11];
    const float* Wfc = (const float*)d_in[12];
    const float* bfc = (const float*)d_in[13];
    const float* Ws  = (const float*)d_in[14];
    const float* bs  = (const float*)d_in[15];
    float* out = (float*)d_out;

    k_all<<<NB, TPB>>>(feats, edges,
                       W1l, b1, W1r, W2l, b2, W2r, W3l, b3, W3r,
                       Watt, Wfc, bfc, Ws, bs, out);
}